// round 1
// baseline (speedup 1.0000x reference)
#include <cuda_runtime.h>
#include <cuda_bf16.h>
#include <math.h>

#define N_NODES 80000
#define E_EDGES 1280000
#define EP_EDGES (E_EDGES + N_NODES)   /* 1,360,000 with self-loops */
#define C 128
#define NHEAD 8
#define NODE_PER_G 10000
#define BATCH 8
#define EB ((EP_EDGES + 255) / 256)    /* 5313 */

// ---------------- device scratch (static: no allocation allowed) ----------------
__device__ float g_h[N_NODES * C];       // h = x @ W^T
__device__ float g_x[N_NODES * C];       // layer activations
__device__ float g_acc[N_NODES * C];     // GAT aggregation output
__device__ float g_adst[N_NODES * NHEAD];
__device__ float g_asrc[N_NODES * NHEAD];
__device__ unsigned g_amax[N_NODES * NHEAD];
__device__ float g_den[N_NODES * NHEAD];
__device__ int g_cnt[N_NODES];
__device__ int g_rowptr[N_NODES + 1];
__device__ int g_cur[N_NODES];
__device__ int g_srcsorted[EP_EDGES];
__device__ int g_bsum[320];
__device__ int g_boff[320];
__device__ float g_bnsum[C], g_bnsq[C], g_scale[C], g_shift[C];
__device__ float g_pool[BATCH * C];

// ---------------- helpers ----------------
__device__ __forceinline__ float lrelu(float a) { return a >= 0.f ? a : 0.2f * a; }
// order-preserving float<->uint encoding for atomicMax on floats (incl. negatives)
__device__ __forceinline__ unsigned fenc(float f) {
    unsigned u = __float_as_uint(f);
    return (u & 0x80000000u) ? ~u : (u | 0x80000000u);
}
__device__ __forceinline__ float fdec(unsigned u) {
    u = (u & 0x80000000u) ? (u & 0x7fffffffu) : ~u;
    return __uint_as_float(u);
}

// ---------------- layer-1 GEMM: h[n][o] = sum_{k<8} x[n][k] * W1[o][k] ----------------
__global__ void k_gemm_in8(const float* __restrict__ xin, const float* __restrict__ W1) {
    int id = blockIdx.x * 256 + threadIdx.x;    // N*C = 10,240,000 = 40000*256
    int n = id >> 7, o = id & 127;
    const float* xr = xin + n * 8;
    const float* wr = W1 + o * 8;
    float a = 0.f;
#pragma unroll
    for (int k = 0; k < 8; k++) a += xr[k] * wr[k];
    g_h[id] = a;
}

// ---------------- 128x128 GEMM: g_h = g_x @ W^T ----------------
__global__ void __launch_bounds__(256) k_gemm128(const float* __restrict__ W) {
    __shared__ float Xs[64][33];
    __shared__ float Ws[32][136];
    int t = threadIdx.x;
    int lane = t & 31;
    int row8 = t >> 5;      // 0..7
    int og = t & 15;        // out group   -> outputs og*8 .. og*8+7
    int ng = t >> 4;        // node group  -> nodes ng*4 .. ng*4+3
    int o0 = og * 8;
    int n0 = blockIdx.x * 64;

    float acc[4][8];
#pragma unroll
    for (int i = 0; i < 4; i++)
#pragma unroll
        for (int q = 0; q < 8; q++) acc[i][q] = 0.f;

    for (int kt = 0; kt < 128; kt += 32) {
#pragma unroll
        for (int p = 0; p < 8; p++) {
            int r = row8 + p * 8;
            Xs[r][lane] = g_x[(n0 + r) * 128 + kt + lane];
        }
#pragma unroll
        for (int p = 0; p < 16; p++) {
            int orow = row8 + p * 8;
            Ws[lane][orow] = W[orow * 128 + kt + lane];   // transposed store
        }
        __syncthreads();
#pragma unroll
        for (int kk = 0; kk < 32; kk++) {
            float4 wa = *(const float4*)&Ws[kk][o0];
            float4 wb = *(const float4*)&Ws[kk][o0 + 4];
#pragma unroll
            for (int i = 0; i < 4; i++) {
                float xv = Xs[ng * 4 + i][kk];
                acc[i][0] += xv * wa.x; acc[i][1] += xv * wa.y;
                acc[i][2] += xv * wa.z; acc[i][3] += xv * wa.w;
                acc[i][4] += xv * wb.x; acc[i][5] += xv * wb.y;
                acc[i][6] += xv * wb.z; acc[i][7] += xv * wb.w;
            }
        }
        __syncthreads();
    }
#pragma unroll
    for (int i = 0; i < 4; i++) {
        int n = n0 + ng * 4 + i;
        float4 v0 = make_float4(acc[i][0], acc[i][1], acc[i][2], acc[i][3]);
        float4 v1 = make_float4(acc[i][4], acc[i][5], acc[i][6], acc[i][7]);
        *(float4*)&g_h[n * 128 + o0] = v0;
        *(float4*)&g_h[n * 128 + o0 + 4] = v1;
    }
}

// ---------------- per-node attention dots ----------------
__global__ void k_attdot(const float* __restrict__ att) {
    __shared__ float A[256];
    int t = threadIdx.x;
    A[t] = att[t];
    __syncthreads();
    int id = blockIdx.x * 256 + t;   // N*H = 640,000 = 2500*256
    int n = id >> 3, h = id & 7;
    const float4* hp = (const float4*)(g_h + n * 128 + h * 16);
    const float* a1 = A + h * 32;
    const float* a2 = a1 + 16;
    float s1 = 0.f, s2 = 0.f;
#pragma unroll
    for (int r = 0; r < 4; r++) {
        float4 v = hp[r];
        s1 += v.x * a1[r*4+0] + v.y * a1[r*4+1] + v.z * a1[r*4+2] + v.w * a1[r*4+3];
        s2 += v.x * a2[r*4+0] + v.y * a2[r*4+1] + v.z * a2[r*4+2] + v.w * a2[r*4+3];
    }
    g_adst[id] = s1;
    g_asrc[id] = s2;
}

// ---------------- CSR build (dst-grouped), feature-independent ----------------
__global__ void k_count(const int* __restrict__ ei) {
    int e = blockIdx.x * 256 + threadIdx.x;
    if (e >= EP_EDGES) return;
    int d = (e < E_EDGES) ? ei[E_EDGES + e] : (e - E_EDGES);
    atomicAdd(&g_cnt[d], 1);
}
__global__ void k_bsum() {  // 313 blocks x 256
    int t = threadIdx.x;
    int idx = blockIdx.x * 256 + t;
    int v = (idx < N_NODES) ? g_cnt[idx] : 0;
    __shared__ int sh[256];
    sh[t] = v; __syncthreads();
    for (int off = 128; off; off >>= 1) { if (t < off) sh[t] += sh[t + off]; __syncthreads(); }
    if (t == 0) g_bsum[blockIdx.x] = sh[0];
}
__global__ void k_bscan() {  // 1 block x 512, exclusive scan of 313 block sums
    __shared__ int sh[512];
    int t = threadIdx.x;
    int v = (t < 313) ? g_bsum[t] : 0;
    sh[t] = v; __syncthreads();
    for (int off = 1; off < 512; off <<= 1) {
        int x = (t >= off) ? sh[t - off] : 0;
        __syncthreads();
        sh[t] += x;
        __syncthreads();
    }
    if (t < 313) g_boff[t] = sh[t] - v;
}
__global__ void k_rowptr() {  // 313 blocks x 256
    int t = threadIdx.x;
    int idx = blockIdx.x * 256 + t;
    int v = (idx < N_NODES) ? g_cnt[idx] : 0;
    __shared__ int sh[256];
    sh[t] = v; __syncthreads();
    for (int off = 1; off < 256; off <<= 1) {
        int x = (t >= off) ? sh[t - off] : 0;
        __syncthreads();
        sh[t] += x;
        __syncthreads();
    }
    int excl = sh[t] - v + g_boff[blockIdx.x];
    if (idx < N_NODES) { g_rowptr[idx] = excl; g_cur[idx] = excl; }
    if (idx == N_NODES - 1) g_rowptr[N_NODES] = excl + v;
}
__global__ void k_scatter(const int* __restrict__ ei) {
    int e = blockIdx.x * 256 + threadIdx.x;
    if (e >= EP_EDGES) return;
    int s, d;
    if (e < E_EDGES) { s = ei[e]; d = ei[E_EDGES + e]; } else { s = d = e - E_EDGES; }
    int pos = atomicAdd(&g_cur[d], 1);
    g_srcsorted[pos] = s;
}

// ---------------- edge softmax passes (grouped by SRC, per reference) ----------------
__global__ void k_edge_max(const int* __restrict__ ei) {
    int e = blockIdx.x * 256 + threadIdx.x;
    if (e >= EP_EDGES) return;
    int s, d;
    if (e < E_EDGES) { s = ei[e]; d = ei[E_EDGES + e]; } else { s = d = e - E_EDGES; }
    float4 ad0 = *(const float4*)(g_adst + d * 8);
    float4 ad1 = *(const float4*)(g_adst + d * 8 + 4);
    float4 as0 = *(const float4*)(g_asrc + s * 8);
    float4 as1 = *(const float4*)(g_asrc + s * 8 + 4);
    unsigned* am = g_amax + s * 8;
    atomicMax(am + 0, fenc(lrelu(ad0.x + as0.x)));
    atomicMax(am + 1, fenc(lrelu(ad0.y + as0.y)));
    atomicMax(am + 2, fenc(lrelu(ad0.z + as0.z)));
    atomicMax(am + 3, fenc(lrelu(ad0.w + as0.w)));
    atomicMax(am + 4, fenc(lrelu(ad1.x + as1.x)));
    atomicMax(am + 5, fenc(lrelu(ad1.y + as1.y)));
    atomicMax(am + 6, fenc(lrelu(ad1.z + as1.z)));
    atomicMax(am + 7, fenc(lrelu(ad1.w + as1.w)));
}
__global__ void k_edge_den(const int* __restrict__ ei) {
    int e = blockIdx.x * 256 + threadIdx.x;
    if (e >= EP_EDGES) return;
    int s, d;
    if (e < E_EDGES) { s = ei[e]; d = ei[E_EDGES + e]; } else { s = d = e - E_EDGES; }
    const float* ad = g_adst + d * 8;
    const float* as = g_asrc + s * 8;
    const unsigned* am = g_amax + s * 8;
    float* dn = g_den + s * 8;
#pragma unroll
    for (int h = 0; h < 8; h++) {
        float a = lrelu(ad[h] + as[h]);
        float w = __expf(a - fdec(am[h]));
        atomicAdd(dn + h, w);
    }
}

// ---------------- gather: one warp per destination node ----------------
__global__ void k_gather() {
    int warp = threadIdx.x >> 5;
    int l = threadIdx.x & 31;
    int d = blockIdx.x * 8 + warp;      // grid = N/8 = 10000
    int h = l >> 2;                     // head owned by this lane's channels
    float adh = g_adst[d * 8 + h];
    int beg = g_rowptr[d], end = g_rowptr[d + 1];
    float4 acc = make_float4(0.f, 0.f, 0.f, 0.f);
    for (int i = beg; i < end; i++) {
        int s = g_srcsorted[i];
        float a = lrelu(adh + g_asrc[s * 8 + h]);
        float w = __expf(a - fdec(g_amax[s * 8 + h])) / (g_den[s * 8 + h] + 1e-16f);
        float4 v = *(const float4*)(g_h + s * 128 + l * 4);
        acc.x += w * v.x; acc.y += w * v.y; acc.z += w * v.z; acc.w += w * v.w;
    }
    *(float4*)(g_acc + d * 128 + l * 4) = acc;
}

// ---------------- batchnorm ----------------
__global__ void k_bnreduce(const float* __restrict__ bias) {
    int t = threadIdx.x;
    int c = t & 127, sub = t >> 7;
    float b = bias[c];
    float s = 0.f, s2 = 0.f;
    for (int n = blockIdx.x * 2 + sub; n < N_NODES; n += gridDim.x * 2) {
        float v = g_acc[n * 128 + c] + b;
        v = fmaxf(v, 0.f);
        s += v; s2 += v * v;
    }
    __shared__ float sh[256], sh2[256];
    sh[t] = s; sh2[t] = s2; __syncthreads();
    if (t < 128) {
        atomicAdd(&g_bnsum[c], sh[t] + sh[t + 128]);
        atomicAdd(&g_bnsq[c], sh2[t] + sh2[t + 128]);
    }
}
__global__ void k_bnfinal(const float* __restrict__ g, const float* __restrict__ be) {
    int c = threadIdx.x;
    float m = g_bnsum[c] / (float)N_NODES;
    float var = g_bnsq[c] / (float)N_NODES - m * m;
    float sc = g[c] * rsqrtf(var + 1e-5f);
    g_scale[c] = sc;
    g_shift[c] = be[c] - m * sc;
}
__global__ void k_bnapply(const float* __restrict__ bias) {
    int id = blockIdx.x * 256 + threadIdx.x;   // grid 40000
    int c = id & 127;
    float v = fmaxf(g_acc[id] + bias[c], 0.f);
    float y = v * g_scale[c] + g_shift[c];
    g_x[id] = (y >= 0.f) ? y : 0.2f * y;
}

// ---------------- power-mean pooling + head ----------------
__global__ void k_poolsum(const float* __restrict__ pp) {
    float p = pp[0];
    int b = blockIdx.y, chunk = blockIdx.x, c = threadIdx.x;  // 128 threads
    float s = 0.f;
    int i0 = chunk * 313;
    int iend = min(i0 + 313, NODE_PER_G);
    for (int i = i0; i < iend; i++) {
        float v = g_x[(b * NODE_PER_G + i) * 128 + c];
        v = fminf(fmaxf(v, 0.f), 100.f);
        if (p != 1.f) v = (v > 0.f) ? __powf(v, p) : 0.f;
        s += v;
    }
    atomicAdd(&g_pool[b * 128 + c], s);
}
__global__ void k_final(float* out, int out_size, const float* __restrict__ pp,
                        const float* __restrict__ Wg, const float* __restrict__ bg) {
    __shared__ float xg[1024];
    __shared__ float lg[16];
    int t = threadIdx.x;   // 1024
    float p = pp[0];
    {
        float m = g_pool[t] * (1.f / (float)NODE_PER_G);
        m = fminf(fmaxf(m, 0.f), 100.f);
        if (p != 1.f) m = (m > 0.f) ? __powf(m, 1.f / p) : 0.f;
        xg[t] = m;
    }
    __syncthreads();
    if (t < 16) {
        int b = t >> 1, cls = t & 1;
        float a = bg[cls];
        const float* w = Wg + cls * 128;
        const float* xr = xg + b * 128;
        for (int c2 = 0; c2 < 128; c2++) a += xr[c2] * w[c2];
        lg[t] = a;
        if (t < out_size) out[t] = a;
    }
    __syncthreads();
    if (t < 8 && (16 + t) < out_size) {
        out[16 + t] = (lg[2 * t + 1] > lg[2 * t]) ? 1.f : 0.f;
    }
}

// ---------------- host driver ----------------
static void run_gat_layer(const int* ei, const float* att, const float* bias,
                          const float* gamma, const float* beta,
                          void* amax_p, void* den_p, void* bns_p, void* bnq_p) {
    k_attdot<<<2500, 256>>>(att);
    cudaMemsetAsync(amax_p, 0, N_NODES * NHEAD * sizeof(unsigned));
    cudaMemsetAsync(den_p, 0, N_NODES * NHEAD * sizeof(float));
    k_edge_max<<<EB, 256>>>(ei);
    k_edge_den<<<EB, 256>>>(ei);
    k_gather<<<N_NODES / 8, 256>>>();
    cudaMemsetAsync(bns_p, 0, C * sizeof(float));
    cudaMemsetAsync(bnq_p, 0, C * sizeof(float));
    k_bnreduce<<<256, 256>>>(bias);
    k_bnfinal<<<1, 128>>>(gamma, beta);
    k_bnapply<<<40000, 256>>>(bias);
}

extern "C" void kernel_launch(void* const* d_in, const int* in_sizes, int n_in,
                              void* d_out, int out_size) {
    const float* x    = (const float*)d_in[0];
    const int*   ei   = (const int*)d_in[1];
    const float* W1   = (const float*)d_in[2];
    const float* att1 = (const float*)d_in[3];
    const float* b1   = (const float*)d_in[4];
    const float* g1   = (const float*)d_in[5];
    const float* be1  = (const float*)d_in[6];
    const float* W2   = (const float*)d_in[7];
    const float* att2 = (const float*)d_in[8];
    const float* b2   = (const float*)d_in[9];
    const float* g2   = (const float*)d_in[10];
    const float* be2  = (const float*)d_in[11];
    const float* W3   = (const float*)d_in[12];
    const float* att3 = (const float*)d_in[13];
    const float* b3   = (const float*)d_in[14];
    const float* g3   = (const float*)d_in[15];
    const float* be3  = (const float*)d_in[16];
    const float* p    = (const float*)d_in[17];
    const float* Wg   = (const float*)d_in[18];
    const float* bg   = (const float*)d_in[19];
    float* out = (float*)d_out;

    void *amax_p, *den_p, *cnt_p, *pool_p, *bns_p, *bnq_p;
    cudaGetSymbolAddress(&amax_p, g_amax);
    cudaGetSymbolAddress(&den_p, g_den);
    cudaGetSymbolAddress(&cnt_p, g_cnt);
    cudaGetSymbolAddress(&pool_p, g_pool);
    cudaGetSymbolAddress(&bns_p, g_bnsum);
    cudaGetSymbolAddress(&bnq_p, g_bnsq);

    // --- CSR by destination (shared by all 3 layers) ---
    cudaMemsetAsync(cnt_p, 0, N_NODES * sizeof(int));
    k_count<<<EB, 256>>>(ei);
    k_bsum<<<313, 256>>>();
    k_bscan<<<1, 512>>>();
    k_rowptr<<<313, 256>>>();
    k_scatter<<<EB, 256>>>(ei);
    cudaMemsetAsync(pool_p, 0, BATCH * C * sizeof(float));

    // --- layer 1 ---
    k_gemm_in8<<<40000, 256>>>(x, W1);
    run_gat_layer(ei, att1, b1, g1, be1, amax_p, den_p, bns_p, bnq_p);
    // --- layer 2 ---
    k_gemm128<<<N_NODES / 64, 256>>>(W2);
    run_gat_layer(ei, att2, b2, g2, be2, amax_p, den_p, bns_p, bnq_p);
    // --- layer 3 ---
    k_gemm128<<<N_NODES / 64, 256>>>(W3);
    run_gat_layer(ei, att3, b3, g3, be3, amax_p, den_p, bns_p, bnq_p);

    // --- pooling + classifier head ---
    k_poolsum<<<dim3(32, BATCH), 128>>>(p);
    k_final<<<1, 1024>>>(out, out_size, p, Wg, bg);
}

// round 2
// speedup vs baseline: 1.8868x; 1.8868x over previous
#include <cuda_runtime.h>
#include <cuda_bf16.h>
#include <math.h>

#define N_NODES 80000
#define E_EDGES 1280000
#define EP_EDGES (E_EDGES + N_NODES)   /* 1,360,000 with self-loops */
#define C 128
#define NHEAD 8
#define NODE_PER_G 10000
#define BATCH 8
#define EB ((EP_EDGES + 255) / 256)    /* 5313 */
#define NB 313                          /* ceil(N/256) */

// ---------------- device scratch (static: no allocation allowed) ----------------
__device__ float g_h[N_NODES * C];       // h = x @ W^T
__device__ float g_acc[N_NODES * C];     // relu(agg + bias)  (layer output pre-BN)
__device__ float g_adst[N_NODES * NHEAD];
__device__ float g_asrc[N_NODES * NHEAD];
__device__ float g_maxa[N_NODES * NHEAD];   // per-src segment max
__device__ float g_rden[N_NODES * NHEAD];   // 1/(den+1e-16)
__device__ int g_cntS[N_NODES];
__device__ int g_cntD[N_NODES];
__device__ int g_rowptrS[N_NODES + 1];
__device__ int g_rowptrD[N_NODES + 1];
__device__ int g_curS[N_NODES];
__device__ int g_curD[N_NODES];
__device__ int g_dstsorted[EP_EDGES];    // dst ids grouped by src
__device__ int g_srcsorted[EP_EDGES];    // src ids grouped by dst
__device__ int g_bsum[320];
__device__ int g_boff[320];
__device__ float g_bnsum[C], g_bnsq[C], g_scale[C], g_shift[C];
__device__ float g_pool[BATCH * C];

__device__ __forceinline__ float lrelu(float a) { return a >= 0.f ? a : 0.2f * a; }

// ============================ CSR build (both directions) ============================
__global__ void k_count(const int* __restrict__ ei) {
    int e = blockIdx.x * 256 + threadIdx.x;
    if (e >= EP_EDGES) return;
    int s, d;
    if (e < E_EDGES) { s = ei[e]; d = ei[E_EDGES + e]; } else { s = d = e - E_EDGES; }
    atomicAdd(&g_cntS[s], 1);
    atomicAdd(&g_cntD[d], 1);
}
__global__ void k_bsum(const int* __restrict__ cnt) {  // NB blocks x 256
    int t = threadIdx.x;
    int idx = blockIdx.x * 256 + t;
    int v = (idx < N_NODES) ? cnt[idx] : 0;
    __shared__ int sh[256];
    sh[t] = v; __syncthreads();
    for (int off = 128; off; off >>= 1) { if (t < off) sh[t] += sh[t + off]; __syncthreads(); }
    if (t == 0) g_bsum[blockIdx.x] = sh[0];
}
__global__ void k_bscan() {  // 1 block x 512
    __shared__ int sh[512];
    int t = threadIdx.x;
    int v = (t < NB) ? g_bsum[t] : 0;
    sh[t] = v; __syncthreads();
    for (int off = 1; off < 512; off <<= 1) {
        int x = (t >= off) ? sh[t - off] : 0;
        __syncthreads();
        sh[t] += x;
        __syncthreads();
    }
    if (t < NB) g_boff[t] = sh[t] - v;
}
__global__ void k_rowptr(int* __restrict__ cnt, int* __restrict__ rowptr, int* __restrict__ cur) {
    int t = threadIdx.x;
    int idx = blockIdx.x * 256 + t;
    int v = (idx < N_NODES) ? cnt[idx] : 0;
    __shared__ int sh[256];
    sh[t] = v; __syncthreads();
    for (int off = 1; off < 256; off <<= 1) {
        int x = (t >= off) ? sh[t - off] : 0;
        __syncthreads();
        sh[t] += x;
        __syncthreads();
    }
    int excl = sh[t] - v + g_boff[blockIdx.x];
    if (idx < N_NODES) { rowptr[idx] = excl; cur[idx] = excl; cnt[idx] = 0; }
    if (idx == N_NODES - 1) rowptr[N_NODES] = excl + v;
}
__global__ void k_scatter(const int* __restrict__ ei) {
    int e = blockIdx.x * 256 + threadIdx.x;
    if (e >= EP_EDGES) return;
    int s, d;
    if (e < E_EDGES) { s = ei[e]; d = ei[E_EDGES + e]; } else { s = d = e - E_EDGES; }
    int ps = atomicAdd(&g_curS[s], 1);
    g_dstsorted[ps] = d;
    int pd = atomicAdd(&g_curD[d], 1);
    g_srcsorted[pd] = s;
}

// ============================ layer-1 GEMM (in_dim=8) + att dots ============================
__global__ void k_gemm_in8(const float* __restrict__ xin, const float* __restrict__ W1,
                           const float* __restrict__ att) {
    __shared__ float A[256];
    A[threadIdx.x] = att[threadIdx.x];
    __syncthreads();
    int id = blockIdx.x * 256 + threadIdx.x;    // N*C = 40000 blocks
    int n = id >> 7, o = id & 127;
    const float* xr = xin + n * 8;
    const float* wr = W1 + o * 8;
    float a = 0.f;
#pragma unroll
    for (int k = 0; k < 8; k++) a += xr[k] * wr[k];
    g_h[id] = a;
    // attention dots: reduce over 16-lane group (one head)
    int head = (o >> 4) & 7;
    int c = o & 15;
    float pd = a * A[head * 32 + c];
    float ps = a * A[head * 32 + 16 + c];
#pragma unroll
    for (int off = 8; off; off >>= 1) {
        pd += __shfl_down_sync(0xffffffffu, pd, off, 16);
        ps += __shfl_down_sync(0xffffffffu, ps, off, 16);
    }
    if (c == 0) { g_adst[n * 8 + head] = pd; g_asrc[n * 8 + head] = ps; }
}

// ============================ 128x128 GEMM w/ fused BN-affine input + att dots ============================
__global__ void __launch_bounds__(256) k_gemm128(const float* __restrict__ W,
                                                 const float* __restrict__ att) {
    __shared__ float Xs[64][33];
    __shared__ float Ws[32][136];
    __shared__ float A[256];
    __shared__ float Ss[128], Hs[128];
    int t = threadIdx.x;
    int lane = t & 31;
    int row8 = t >> 5;      // 0..7
    int og = t & 15;
    int ng = t >> 4;
    int o0 = og * 8;
    int n0 = blockIdx.x * 64;

    A[t] = att[t];
    if (t < 128) { Ss[t] = g_scale[t]; Hs[t] = g_shift[t]; }
    __syncthreads();

    float acc[4][8];
#pragma unroll
    for (int i = 0; i < 4; i++)
#pragma unroll
        for (int q = 0; q < 8; q++) acc[i][q] = 0.f;

    for (int kt = 0; kt < 128; kt += 32) {
        float sc = Ss[kt + lane], sh = Hs[kt + lane];
#pragma unroll
        for (int p = 0; p < 8; p++) {
            int r = row8 + p * 8;
            float v = g_acc[(n0 + r) * 128 + kt + lane];   // already relu(agg+bias)
            float y = v * sc + sh;
            Xs[r][lane] = (y >= 0.f) ? y : 0.2f * y;
        }
#pragma unroll
        for (int p = 0; p < 16; p++) {
            int orow = row8 + p * 8;
            Ws[lane][orow] = W[orow * 128 + kt + lane];
        }
        __syncthreads();
#pragma unroll
        for (int kk = 0; kk < 32; kk++) {
            float4 wa = *(const float4*)&Ws[kk][o0];
            float4 wb = *(const float4*)&Ws[kk][o0 + 4];
#pragma unroll
            for (int i = 0; i < 4; i++) {
                float xv = Xs[ng * 4 + i][kk];
                acc[i][0] += xv * wa.x; acc[i][1] += xv * wa.y;
                acc[i][2] += xv * wa.z; acc[i][3] += xv * wa.w;
                acc[i][4] += xv * wb.x; acc[i][5] += xv * wb.y;
                acc[i][6] += xv * wb.z; acc[i][7] += xv * wb.w;
            }
        }
        __syncthreads();
    }
    int head = og >> 1;
    int c0 = (og & 1) * 8;
#pragma unroll
    for (int i = 0; i < 4; i++) {
        int n = n0 + ng * 4 + i;
        *(float4*)&g_h[n * 128 + o0]     = make_float4(acc[i][0], acc[i][1], acc[i][2], acc[i][3]);
        *(float4*)&g_h[n * 128 + o0 + 4] = make_float4(acc[i][4], acc[i][5], acc[i][6], acc[i][7]);
        float pd = 0.f, ps = 0.f;
#pragma unroll
        for (int q = 0; q < 8; q++) {
            pd += acc[i][q] * A[head * 32 + c0 + q];
            ps += acc[i][q] * A[head * 32 + 16 + c0 + q];
        }
        pd += __shfl_xor_sync(0xffffffffu, pd, 1);
        ps += __shfl_xor_sync(0xffffffffu, ps, 1);
        if (!(og & 1)) { g_adst[n * 8 + head] = pd; g_asrc[n * 8 + head] = ps; }
    }
}

// ============================ src-grouped softmax: exact segment max + sum ============================
__global__ void k_srcsoft() {
    int id = blockIdx.x * 256 + threadIdx.x;   // 2500 blocks, thread = (src, head)
    int s = id >> 3, h = id & 7;
    float as = g_asrc[id];
    int beg = g_rowptrS[s], end = g_rowptrS[s + 1];
    float mx = -1e30f;
    int i = beg;
    for (; i + 2 <= end; i += 2) {
        int d0 = g_dstsorted[i], d1 = g_dstsorted[i + 1];
        float a0 = lrelu(g_adst[d0 * 8 + h] + as);
        float a1 = lrelu(g_adst[d1 * 8 + h] + as);
        mx = fmaxf(mx, fmaxf(a0, a1));
    }
    if (i < end) {
        int d = g_dstsorted[i];
        mx = fmaxf(mx, lrelu(g_adst[d * 8 + h] + as));
    }
    float den = 0.f;
    i = beg;
    for (; i + 2 <= end; i += 2) {
        int d0 = g_dstsorted[i], d1 = g_dstsorted[i + 1];
        float a0 = lrelu(g_adst[d0 * 8 + h] + as);
        float a1 = lrelu(g_adst[d1 * 8 + h] + as);
        den += __expf(a0 - mx) + __expf(a1 - mx);
    }
    if (i < end) {
        int d = g_dstsorted[i];
        den += __expf(lrelu(g_adst[d * 8 + h] + as) - mx);
    }
    g_maxa[id] = mx;
    g_rden[id] = 1.f / (den + 1e-16f);
}

// ============================ gather: one warp per destination node ============================
__global__ void k_gather(const float* __restrict__ bias) {
    int warp = threadIdx.x >> 5;
    int l = threadIdx.x & 31;
    int d = blockIdx.x * 8 + warp;      // grid = N/8
    int h = l >> 2;
    float adh = g_adst[d * 8 + h];
    int i = g_rowptrD[d], end = g_rowptrD[d + 1];
    float4 acc = make_float4(0.f, 0.f, 0.f, 0.f);
    for (; i + 2 <= end; i += 2) {
        int s0 = g_srcsorted[i];
        int s1 = g_srcsorted[i + 1];
        float as0 = g_asrc[s0 * 8 + h], mx0 = g_maxa[s0 * 8 + h], rd0 = g_rden[s0 * 8 + h];
        float as1 = g_asrc[s1 * 8 + h], mx1 = g_maxa[s1 * 8 + h], rd1 = g_rden[s1 * 8 + h];
        float4 v0 = *(const float4*)(g_h + s0 * 128 + l * 4);
        float4 v1 = *(const float4*)(g_h + s1 * 128 + l * 4);
        float w0 = __expf(lrelu(adh + as0) - mx0) * rd0;
        float w1 = __expf(lrelu(adh + as1) - mx1) * rd1;
        acc.x += w0 * v0.x + w1 * v1.x;
        acc.y += w0 * v0.y + w1 * v1.y;
        acc.z += w0 * v0.z + w1 * v1.z;
        acc.w += w0 * v0.w + w1 * v1.w;
    }
    if (i < end) {
        int s = g_srcsorted[i];
        float as = g_asrc[s * 8 + h], mx = g_maxa[s * 8 + h], rd = g_rden[s * 8 + h];
        float4 v = *(const float4*)(g_h + s * 128 + l * 4);
        float w = __expf(lrelu(adh + as) - mx) * rd;
        acc.x += w * v.x; acc.y += w * v.y; acc.z += w * v.z; acc.w += w * v.w;
    }
    float4 b4 = *(const float4*)(bias + l * 4);
    acc.x = fmaxf(acc.x + b4.x, 0.f);
    acc.y = fmaxf(acc.y + b4.y, 0.f);
    acc.z = fmaxf(acc.z + b4.z, 0.f);
    acc.w = fmaxf(acc.w + b4.w, 0.f);
    *(float4*)(g_acc + d * 128 + l * 4) = acc;
}

// ============================ batchnorm stats (input already relu(agg+bias)) ============================
__global__ void k_bnreduce() {
    int t = threadIdx.x;
    int c = t & 127, sub = t >> 7;
    float s = 0.f, s2 = 0.f;
    for (int n = blockIdx.x * 2 + sub; n < N_NODES; n += gridDim.x * 2) {
        float v = g_acc[n * 128 + c];
        s += v; s2 += v * v;
    }
    __shared__ float sh[256], sh2[256];
    sh[t] = s; sh2[t] = s2; __syncthreads();
    if (t < 128) {
        atomicAdd(&g_bnsum[c], sh[t] + sh[t + 128]);
        atomicAdd(&g_bnsq[c], sh2[t] + sh2[t + 128]);
    }
}
__global__ void k_bnfinal(const float* __restrict__ g, const float* __restrict__ be) {
    int c = threadIdx.x;
    float m = g_bnsum[c] / (float)N_NODES;
    float var = g_bnsq[c] / (float)N_NODES - m * m;
    float sc = g[c] * rsqrtf(var + 1e-5f);
    g_scale[c] = sc;
    g_shift[c] = be[c] - m * sc;
    g_bnsum[c] = 0.f;     // re-zero for next use (and next graph replay)
    g_bnsq[c] = 0.f;
}

// ============================ power-mean pooling (BN affine fused) + head ============================
__global__ void k_poolsum(const float* __restrict__ pp) {
    float p = pp[0];
    int b = blockIdx.y, chunk = blockIdx.x, c = threadIdx.x;  // 128 threads
    float sc = g_scale[c], sh = g_shift[c];
    float s = 0.f;
    int i0 = chunk * 313;
    int iend = min(i0 + 313, NODE_PER_G);
    for (int i = i0; i < iend; i++) {
        float v = g_acc[(b * NODE_PER_G + i) * 128 + c];
        float y = v * sc + sh;
        y = (y >= 0.f) ? y : 0.2f * y;
        y = fminf(fmaxf(y, 0.f), 100.f);
        if (p != 1.f) y = (y > 0.f) ? __powf(y, p) : 0.f;
        s += y;
    }
    atomicAdd(&g_pool[b * 128 + c], s);
}
__global__ void k_final(float* out, int out_size, const float* __restrict__ pp,
                        const float* __restrict__ Wg, const float* __restrict__ bg) {
    __shared__ float xg[1024];
    __shared__ float lg[16];
    int t = threadIdx.x;   // 1024
    float p = pp[0];
    {
        float m = g_pool[t] * (1.f / (float)NODE_PER_G);
        g_pool[t] = 0.f;   // re-zero for next graph replay
        m = fminf(fmaxf(m, 0.f), 100.f);
        if (p != 1.f) m = (m > 0.f) ? __powf(m, 1.f / p) : 0.f;
        xg[t] = m;
    }
    __syncthreads();
    if (t < 16) {
        int b = t >> 1, cls = t & 1;
        float a = bg[cls];
        const float* w = Wg + cls * 128;
        const float* xr = xg + b * 128;
        for (int c2 = 0; c2 < 128; c2++) a += xr[c2] * w[c2];
        lg[t] = a;
        if (t < out_size) out[t] = a;
    }
    __syncthreads();
    if (t < 8 && (16 + t) < out_size) {
        out[16 + t] = (lg[2 * t + 1] > lg[2 * t]) ? 1.f : 0.f;
    }
}

// ============================ host driver ============================
extern "C" void kernel_launch(void* const* d_in, const int* in_sizes, int n_in,
                              void* d_out, int out_size) {
    const float* x    = (const float*)d_in[0];
    const int*   ei   = (const int*)d_in[1];
    const float* W1   = (const float*)d_in[2];
    const float* att1 = (const float*)d_in[3];
    const float* b1   = (const float*)d_in[4];
    const float* g1   = (const float*)d_in[5];
    const float* be1  = (const float*)d_in[6];
    const float* W2   = (const float*)d_in[7];
    const float* att2 = (const float*)d_in[8];
    const float* b2   = (const float*)d_in[9];
    const float* g2   = (const float*)d_in[10];
    const float* be2  = (const float*)d_in[11];
    const float* W3   = (const float*)d_in[12];
    const float* att3 = (const float*)d_in[13];
    const float* b3   = (const float*)d_in[14];
    const float* g3   = (const float*)d_in[15];
    const float* be3  = (const float*)d_in[16];
    const float* p    = (const float*)d_in[17];
    const float* Wg   = (const float*)d_in[18];
    const float* bg   = (const float*)d_in[19];
    float* out = (float*)d_out;

    void *cntS_p, *cntD_p, *rpS_p, *rpD_p, *curS_p, *curD_p;
    cudaGetSymbolAddress(&cntS_p, g_cntS);
    cudaGetSymbolAddress(&cntD_p, g_cntD);
    cudaGetSymbolAddress(&rpS_p, g_rowptrS);
    cudaGetSymbolAddress(&rpD_p, g_rowptrD);
    cudaGetSymbolAddress(&curS_p, g_curS);
    cudaGetSymbolAddress(&curD_p, g_curD);

    // --- CSR build (both directions, structure shared by all 3 layers) ---
    k_count<<<EB, 256>>>(ei);
    k_bsum<<<NB, 256>>>((const int*)cntS_p);
    k_bscan<<<1, 512>>>();
    k_rowptr<<<NB, 256>>>((int*)cntS_p, (int*)rpS_p, (int*)curS_p);
    k_bsum<<<NB, 256>>>((const int*)cntD_p);
    k_bscan<<<1, 512>>>();
    k_rowptr<<<NB, 256>>>((int*)cntD_p, (int*)rpD_p, (int*)curD_p);
    k_scatter<<<EB, 256>>>(ei);

    // --- layer 1 ---
    k_gemm_in8<<<40000, 256>>>(x, W1, att1);
    k_srcsoft<<<2500, 256>>>();
    k_gather<<<N_NODES / 8, 256>>>(b1);
    k_bnreduce<<<256, 256>>>();
    k_bnfinal<<<1, 128>>>(g1, be1);
    // --- layer 2 ---
    k_gemm128<<<N_NODES / 64, 256>>>(W2, att2);
    k_srcsoft<<<2500, 256>>>();
    k_gather<<<N_NODES / 8, 256>>>(b2);
    k_bnreduce<<<256, 256>>>();
    k_bnfinal<<<1, 128>>>(g2, be2);
    // --- layer 3 ---
    k_gemm128<<<N_NODES / 64, 256>>>(W3, att3);
    k_srcsoft<<<2500, 256>>>();
    k_gather<<<N_NODES / 8, 256>>>(b3);
    k_bnreduce<<<256, 256>>>();
    k_bnfinal<<<1, 128>>>(g3, be3);

    // --- pooling + classifier head ---
    k_poolsum<<<dim3(32, BATCH), 128>>>(p);
    k_final<<<1, 1024>>>(out, out_size, p, Wg, bg);
}

// round 4
// speedup vs baseline: 2.3492x; 1.2451x over previous
#include <cuda_runtime.h>
#include <cuda_fp16.h>
#include <math.h>

#define N_NODES 80000
#define E_EDGES 1280000
#define EP_EDGES (E_EDGES + N_NODES)   /* 1,360,000 with self-loops */
#define C 128
#define NHEAD 8
#define NODE_PER_G 10000
#define BATCH 8
#define EB ((EP_EDGES + 255) / 256)    /* 5313 */
#define NB 313                          /* ceil(N/256) */

// ---------------- device scratch (static: no allocation allowed) ----------------
__device__ __half g_h[N_NODES * C];      // h = x @ W^T (fp16 storage, fp32 compute)
__device__ __half g_acc[N_NODES * C];    // relu(agg + bias) (fp16)
__device__ float g_adst[N_NODES * NHEAD];
__device__ float g_asrc[N_NODES * NHEAD];
__device__ float g_rden[N_NODES * NHEAD];   // 1/(sum exp + 1e-16)
__device__ int g_cntS[N_NODES];
__device__ int g_cntD[N_NODES];
__device__ int g_rowptrS[N_NODES + 1];
__device__ int g_rowptrD[N_NODES + 1];
__device__ int g_curS[N_NODES];
__device__ int g_curD[N_NODES];
__device__ int g_dstsorted[EP_EDGES];    // dst ids grouped by src
__device__ int g_srcsorted[EP_EDGES];    // src ids grouped by dst
__device__ int g_bsumS[320], g_bsumD[320];
__device__ int g_boffS[320], g_boffD[320];
__device__ float g_bnsum[C], g_bnsq[C], g_scale[C], g_shift[C];
__device__ float g_pool[BATCH * C];

__device__ __forceinline__ float lrelu(float a) { return a >= 0.f ? a : 0.2f * a; }
__device__ __forceinline__ unsigned h2_to_u(__half2 h) {
    union { __half2 h; unsigned u; } cv; cv.h = h; return cv.u;
}

// ============================ CSR build (both directions) ============================
__global__ void k_count(const int* __restrict__ ei) {
    int e = blockIdx.x * 256 + threadIdx.x;
    if (e >= EP_EDGES) return;
    int s, d;
    if (e < E_EDGES) { s = ei[e]; d = ei[E_EDGES + e]; } else { s = d = e - E_EDGES; }
    atomicAdd(&g_cntS[s], 1);
    atomicAdd(&g_cntD[d], 1);
}
__global__ void k_bsum2() {  // NB blocks x 256, both directions
    int t = threadIdx.x;
    int idx = blockIdx.x * 256 + t;
    int vs = (idx < N_NODES) ? g_cntS[idx] : 0;
    int vd = (idx < N_NODES) ? g_cntD[idx] : 0;
    __shared__ int shs[256], shd[256];
    shs[t] = vs; shd[t] = vd; __syncthreads();
    for (int off = 128; off; off >>= 1) {
        if (t < off) { shs[t] += shs[t + off]; shd[t] += shd[t + off]; }
        __syncthreads();
    }
    if (t == 0) { g_bsumS[blockIdx.x] = shs[0]; g_bsumD[blockIdx.x] = shd[0]; }
}
__global__ void k_bscan2() {  // 1 block x 512, both directions
    __shared__ int sh[512];
    int t = threadIdx.x;
    int vs = (t < NB) ? g_bsumS[t] : 0;
    sh[t] = vs; __syncthreads();
    for (int off = 1; off < 512; off <<= 1) {
        int x = (t >= off) ? sh[t - off] : 0; __syncthreads();
        sh[t] += x; __syncthreads();
    }
    if (t < NB) g_boffS[t] = sh[t] - vs;
    __syncthreads();
    int vd = (t < NB) ? g_bsumD[t] : 0;
    sh[t] = vd; __syncthreads();
    for (int off = 1; off < 512; off <<= 1) {
        int x = (t >= off) ? sh[t - off] : 0; __syncthreads();
        sh[t] += x; __syncthreads();
    }
    if (t < NB) g_boffD[t] = sh[t] - vd;
}
__global__ void k_rowptr2() {
    int t = threadIdx.x;
    int idx = blockIdx.x * 256 + t;
    __shared__ int sh[256];
    // --- S direction ---
    int v = (idx < N_NODES) ? g_cntS[idx] : 0;
    sh[t] = v; __syncthreads();
    for (int off = 1; off < 256; off <<= 1) {
        int x = (t >= off) ? sh[t - off] : 0; __syncthreads();
        sh[t] += x; __syncthreads();
    }
    int excl = sh[t] - v + g_boffS[blockIdx.x];
    if (idx < N_NODES) { g_rowptrS[idx] = excl; g_curS[idx] = excl; g_cntS[idx] = 0; }
    if (idx == N_NODES - 1) g_rowptrS[N_NODES] = excl + v;
    __syncthreads();
    // --- D direction ---
    v = (idx < N_NODES) ? g_cntD[idx] : 0;
    sh[t] = v; __syncthreads();
    for (int off = 1; off < 256; off <<= 1) {
        int x = (t >= off) ? sh[t - off] : 0; __syncthreads();
        sh[t] += x; __syncthreads();
    }
    excl = sh[t] - v + g_boffD[blockIdx.x];
    if (idx < N_NODES) { g_rowptrD[idx] = excl; g_curD[idx] = excl; g_cntD[idx] = 0; }
    if (idx == N_NODES - 1) g_rowptrD[N_NODES] = excl + v;
}
__global__ void k_scatter(const int* __restrict__ ei) {
    int e = blockIdx.x * 256 + threadIdx.x;
    if (e >= EP_EDGES) return;
    int s, d;
    if (e < E_EDGES) { s = ei[e]; d = ei[E_EDGES + e]; } else { s = d = e - E_EDGES; }
    int ps = atomicAdd(&g_curS[s], 1);
    g_dstsorted[ps] = d;
    int pd = atomicAdd(&g_curD[d], 1);
    g_srcsorted[pd] = s;
}

// ============================ layer-1 GEMM (in_dim=8) + att dots ============================
__global__ void k_gemm_in8(const float* __restrict__ xin, const float* __restrict__ W1,
                           const float* __restrict__ att) {
    __shared__ float A[256];
    A[threadIdx.x] = att[threadIdx.x];
    __syncthreads();
    int id = blockIdx.x * 256 + threadIdx.x;    // 40000 blocks
    int n = id >> 7, o = id & 127;
    const float* xr = xin + n * 8;
    const float* wr = W1 + o * 8;
    float a = 0.f;
#pragma unroll
    for (int k = 0; k < 8; k++) a += xr[k] * wr[k];
    g_h[id] = __float2half_rn(a);
    int head = (o >> 4) & 7;
    int c = o & 15;
    float pd = a * A[head * 32 + c];
    float ps = a * A[head * 32 + 16 + c];
#pragma unroll
    for (int off = 8; off; off >>= 1) {
        pd += __shfl_down_sync(0xffffffffu, pd, off, 16);
        ps += __shfl_down_sync(0xffffffffu, ps, off, 16);
    }
    if (c == 0) { g_adst[n * 8 + head] = pd; g_asrc[n * 8 + head] = ps; }
}

// ============================ 128x128 GEMM w/ fused BN-affine input + att dots ============================
__global__ void __launch_bounds__(256) k_gemm128(const float* __restrict__ W,
                                                 const float* __restrict__ att) {
    __shared__ float Xs[64][33];
    __shared__ float Ws[32][136];
    __shared__ float A[256];
    __shared__ float Ss[128], Hs[128];
    int t = threadIdx.x;
    int lane = t & 31;
    int row8 = t >> 5;
    int og = t & 15;
    int ng = t >> 4;
    int o0 = og * 8;
    int n0 = blockIdx.x * 64;

    A[t] = att[t];
    if (t < 128) { Ss[t] = g_scale[t]; Hs[t] = g_shift[t]; }
    __syncthreads();

    float acc[4][8];
#pragma unroll
    for (int i = 0; i < 4; i++)
#pragma unroll
        for (int q = 0; q < 8; q++) acc[i][q] = 0.f;

    for (int kt = 0; kt < 128; kt += 32) {
        float sc = Ss[kt + lane], sh = Hs[kt + lane];
#pragma unroll
        for (int p = 0; p < 8; p++) {
            int r = row8 + p * 8;
            float v = __half2float(g_acc[(n0 + r) * 128 + kt + lane]);
            float y = v * sc + sh;
            Xs[r][lane] = (y >= 0.f) ? y : 0.2f * y;
        }
#pragma unroll
        for (int p = 0; p < 16; p++) {
            int orow = row8 + p * 8;
            Ws[lane][orow] = W[orow * 128 + kt + lane];
        }
        __syncthreads();
#pragma unroll
        for (int kk = 0; kk < 32; kk++) {
            float4 wa = *(const float4*)&Ws[kk][o0];
            float4 wb = *(const float4*)&Ws[kk][o0 + 4];
#pragma unroll
            for (int i = 0; i < 4; i++) {
                float xv = Xs[ng * 4 + i][kk];
                acc[i][0] += xv * wa.x; acc[i][1] += xv * wa.y;
                acc[i][2] += xv * wa.z; acc[i][3] += xv * wa.w;
                acc[i][4] += xv * wb.x; acc[i][5] += xv * wb.y;
                acc[i][6] += xv * wb.z; acc[i][7] += xv * wb.w;
            }
        }
        __syncthreads();
    }
    int head = og >> 1;
    int c0 = (og & 1) * 8;
#pragma unroll
    for (int i = 0; i < 4; i++) {
        int n = n0 + ng * 4 + i;
        uint4 pack;
        pack.x = h2_to_u(__floats2half2_rn(acc[i][0], acc[i][1]));
        pack.y = h2_to_u(__floats2half2_rn(acc[i][2], acc[i][3]));
        pack.z = h2_to_u(__floats2half2_rn(acc[i][4], acc[i][5]));
        pack.w = h2_to_u(__floats2half2_rn(acc[i][6], acc[i][7]));
        *(uint4*)(g_h + n * 128 + o0) = pack;
        float pd = 0.f, ps = 0.f;
#pragma unroll
        for (int q = 0; q < 8; q++) {
            pd += acc[i][q] * A[head * 32 + c0 + q];
            ps += acc[i][q] * A[head * 32 + 16 + c0 + q];
        }
        pd += __shfl_xor_sync(0xffffffffu, pd, 1);
        ps += __shfl_xor_sync(0xffffffffu, ps, 1);
        if (!(og & 1)) { g_adst[n * 8 + head] = pd; g_asrc[n * 8 + head] = ps; }
    }
}

// ============================ src-grouped softmax: single pass (no max needed) ============================
__global__ void k_srcsoft() {
    int id = blockIdx.x * 256 + threadIdx.x;   // 2500 blocks, thread = (src, head)
    int s = id >> 3, h = id & 7;
    float as = g_asrc[id];
    int beg = g_rowptrS[s], end = g_rowptrS[s + 1];
    float den = 0.f;
    int i = beg;
    for (; i + 2 <= end; i += 2) {
        int d0 = g_dstsorted[i], d1 = g_dstsorted[i + 1];
        float a0 = lrelu(g_adst[d0 * 8 + h] + as);
        float a1 = lrelu(g_adst[d1 * 8 + h] + as);
        den += __expf(a0) + __expf(a1);
    }
    if (i < end) {
        int d = g_dstsorted[i];
        den += __expf(lrelu(g_adst[d * 8 + h] + as));
    }
    g_rden[id] = 1.f / (den + 1e-16f);
}

// ============================ gather: one warp per destination node ============================
__device__ __forceinline__ void acc_half4(float4& acc, unsigned lo, unsigned hi, float w) {
    union { unsigned u; __half2 h; } a, b;
    a.u = lo; b.u = hi;
    float2 fa = __half22float2(a.h);
    float2 fb = __half22float2(b.h);
    acc.x += w * fa.x; acc.y += w * fa.y; acc.z += w * fb.x; acc.w += w * fb.y;
}
__global__ void k_gather(const float* __restrict__ bias) {
    int warp = threadIdx.x >> 5;
    int l = threadIdx.x & 31;
    int d = blockIdx.x * 8 + warp;      // grid = N/8
    int h = l >> 2;
    float adh = g_adst[d * 8 + h];
    int i = g_rowptrD[d], end = g_rowptrD[d + 1];
    float4 acc = make_float4(0.f, 0.f, 0.f, 0.f);
    for (; i + 2 <= end; i += 2) {
        int s0 = g_srcsorted[i];
        int s1 = g_srcsorted[i + 1];
        float w0 = __expf(lrelu(adh + g_asrc[s0 * 8 + h])) * g_rden[s0 * 8 + h];
        float w1 = __expf(lrelu(adh + g_asrc[s1 * 8 + h])) * g_rden[s1 * 8 + h];
        uint2 p0 = *(const uint2*)(g_h + s0 * 128 + l * 4);
        uint2 p1 = *(const uint2*)(g_h + s1 * 128 + l * 4);
        acc_half4(acc, p0.x, p0.y, w0);
        acc_half4(acc, p1.x, p1.y, w1);
    }
    if (i < end) {
        int s = g_srcsorted[i];
        float w = __expf(lrelu(adh + g_asrc[s * 8 + h])) * g_rden[s * 8 + h];
        uint2 p = *(const uint2*)(g_h + s * 128 + l * 4);
        acc_half4(acc, p.x, p.y, w);
    }
    float4 b4 = *(const float4*)(bias + l * 4);
    uint2 pack;
    pack.x = h2_to_u(__floats2half2_rn(fmaxf(acc.x + b4.x, 0.f), fmaxf(acc.y + b4.y, 0.f)));
    pack.y = h2_to_u(__floats2half2_rn(fmaxf(acc.z + b4.z, 0.f), fmaxf(acc.w + b4.w, 0.f)));
    *(uint2*)(g_acc + d * 128 + l * 4) = pack;
}

// ============================ batchnorm stats ============================
__global__ void k_bnreduce() {
    int t = threadIdx.x;
    int c = t & 127, sub = t >> 7;
    float s = 0.f, s2 = 0.f;
    for (int n = blockIdx.x * 2 + sub; n < N_NODES; n += gridDim.x * 2) {
        float v = __half2float(g_acc[n * 128 + c]);
        s += v; s2 += v * v;
    }
    __shared__ float sh[256], sh2[256];
    sh[t] = s; sh2[t] = s2; __syncthreads();
    if (t < 128) {
        atomicAdd(&g_bnsum[c], sh[t] + sh[t + 128]);
        atomicAdd(&g_bnsq[c], sh2[t] + sh2[t + 128]);
    }
}
__global__ void k_bnfinal(const float* __restrict__ g, const float* __restrict__ be) {
    int c = threadIdx.x;
    float m = g_bnsum[c] / (float)N_NODES;
    float var = g_bnsq[c] / (float)N_NODES - m * m;
    float sc = g[c] * rsqrtf(var + 1e-5f);
    g_scale[c] = sc;
    g_shift[c] = be[c] - m * sc;
    g_bnsum[c] = 0.f;
    g_bnsq[c] = 0.f;
}

// ============================ power-mean pooling (BN affine fused) + head ============================
__global__ void k_poolsum(const float* __restrict__ pp) {
    float p = pp[0];
    int b = blockIdx.y, chunk = blockIdx.x, c = threadIdx.x;  // 128 threads
    float sc = g_scale[c], sh = g_shift[c];
    float s = 0.f;
    int i0 = chunk * 313;
    int iend = min(i0 + 313, NODE_PER_G);
    for (int i = i0; i < iend; i++) {
        float v = __half2float(g_acc[(b * NODE_PER_G + i) * 128 + c]);
        float y = v * sc + sh;
        y = (y >= 0.f) ? y : 0.2f * y;
        y = fminf(fmaxf(y, 0.f), 100.f);
        if (p != 1.f) y = (y > 0.f) ? __powf(y, p) : 0.f;
        s += y;
    }
    atomicAdd(&g_pool[b * 128 + c], s);
}
__global__ void k_final(float* out, int out_size, const float* __restrict__ pp,
                        const float* __restrict__ Wg, const float* __restrict__ bg) {
    __shared__ float xg[1024];
    __shared__ float lg[16];
    int t = threadIdx.x;   // 1024
    float p = pp[0];
    {
        float m = g_pool[t] * (1.f / (float)NODE_PER_G);
        g_pool[t] = 0.f;   // re-zero for next graph replay
        m = fminf(fmaxf(m, 0.f), 100.f);
        if (p != 1.f) m = (m > 0.f) ? __powf(m, 1.f / p) : 0.f;
        xg[t] = m;
    }
    __syncthreads();
    if (t < 16) {
        int b = t >> 1, cls = t & 1;
        float a = bg[cls];
        const float* w = Wg + cls * 128;
        const float* xr = xg + b * 128;
        for (int c2 = 0; c2 < 128; c2++) a += xr[c2] * w[c2];
        lg[t] = a;
        if (t < out_size) out[t] = a;
    }
    __syncthreads();
    if (t < 8 && (16 + t) < out_size) {
        out[16 + t] = (lg[2 * t + 1] > lg[2 * t]) ? 1.f : 0.f;
    }
}

// ============================ host driver ============================
extern "C" void kernel_launch(void* const* d_in, const int* in_sizes, int n_in,
                              void* d_out, int out_size) {
    const float* x    = (const float*)d_in[0];
    const int*   ei   = (const int*)d_in[1];
    const float* W1   = (const float*)d_in[2];
    const float* att1 = (const float*)d_in[3];
    const float* b1   = (const float*)d_in[4];
    const float* g1   = (const float*)d_in[5];
    const float* be1  = (const float*)d_in[6];
    const float* W2   = (const float*)d_in[7];
    const float* att2 = (const float*)d_in[8];
    const float* b2   = (const float*)d_in[9];
    const float* g2   = (const float*)d_in[10];
    const float* be2  = (const float*)d_in[11];
    const float* W3   = (const float*)d_in[12];
    const float* att3 = (const float*)d_in[13];
    const float* b3   = (const float*)d_in[14];
    const float* g3   = (const float*)d_in[15];
    const float* be3  = (const float*)d_in[16];
    const float* p    = (const float*)d_in[17];
    const float* Wg   = (const float*)d_in[18];
    const float* bg   = (const float*)d_in[19];
    float* out = (float*)d_out;

    // --- layer-1 GEMM first (independent of CSR) ---
    k_gemm_in8<<<40000, 256>>>(x, W1, att1);

    // --- CSR build (both directions in shared kernels) ---
    k_count<<<EB, 256>>>(ei);
    k_bsum2<<<NB, 256>>>();
    k_bscan2<<<1, 512>>>();
    k_rowptr2<<<NB, 256>>>();
    k_scatter<<<EB, 256>>>(ei);

    // --- layer 1 ---
    k_srcsoft<<<2500, 256>>>();
    k_gather<<<N_NODES / 8, 256>>>(b1);
    k_bnreduce<<<256, 256>>>();
    k_bnfinal<<<1, 128>>>(g1, be1);
    // --- layer 2 ---
    k_gemm128<<<N_NODES / 64, 256>>>(W2, att2);
    k_srcsoft<<<2500, 256>>>();
    k_gather<<<N_NODES / 8, 256>>>(b2);
    k_bnreduce<<<256, 256>>>();
    k_bnfinal<<<1, 128>>>(g2, be2);
    // --- layer 3 ---
    k_gemm128<<<N_NODES / 64, 256>>>(W3, att3);
    k_srcsoft<<<2500, 256>>>();
    k_gather<<<N_NODES / 8, 256>>>(b3);
    k_bnreduce<<<256, 256>>>();
    k_bnfinal<<<1, 128>>>(g3, be3);

    // --- pooling + classifier head ---
    k_poolsum<<<dim3(32, BATCH), 128>>>(p);
    k_final<<<1, 1024>>>(out, out_size, p, Wg, bg);
}